// round 11
// baseline (speedup 1.0000x reference)
#include <cuda_runtime.h>
#include <cuda_bf16.h>

// SoftEmbeddedDecisionRules: balanced binary hierarchy over C=1024 classes.
// Zero-smem design: one row per warp; lane L owns 8 contiguous classes per
// 256-span: [256j + 8L, 256j+8L+8), j=0..3, loaded as two adjacent float4.
// Levels seg 1/2/4 lane-local; seg 8..128 via shfl butterfly on 8-sums;
// seg 256/512 lane-uniform. No shared memory, no barriers.
// sigmoid via single-MUFU tanh.approx: sigmoid(x) = 0.5*tanh(x/2) + 0.5
// (the 1/2 is folded into each level's mean-scale constant).

#define BATCH_N 32768
#define NCLASS 1024

// sigmoid(d / seg) computed as 0.5*tanh(d * (1/(2*seg))) + 0.5
__device__ __forceinline__ float sigmoid_scaled(float d, float inv2seg) {
    float t;
    asm("tanh.approx.f32 %0, %1;" : "=f"(t) : "f"(d * inv2seg));
    return fmaf(0.5f, t, 0.5f);
}

__global__ void __launch_bounds__(256, 6)
soft_tree_kernel(const float* __restrict__ in, float* __restrict__ out) {
    const int warp = (blockIdx.x * blockDim.x + threadIdx.x) >> 5;
    const int lane = threadIdx.x & 31;

    const float4* gin  = reinterpret_cast<const float4*>(in  + (size_t)warp * NCLASS);
    float4*       gout = reinterpret_cast<float4*>(out + (size_t)warp * NCLASS);

    float fl[16];   // leaf factors (4 per 256-span)
    float a2h[8];   // seg=2 factors (2 per span)
    float a4h[4];   // seg=4 factors (1 per span)
    float Bf[4];    // butterfly product seg 8..128 (per span, per lane)
    float Rs[4];    // 256-span sums (lane-uniform)

#pragma unroll
    for (int j = 0; j < 4; j++) {
        float4 qa = gin[j * 64 + 2 * lane];
        float4 qb = gin[j * 64 + 2 * lane + 1];

        // seg=1 (leaves): sigmoid(x-y) = 0.5*tanh((x-y)/2)+0.5
        fl[4 * j + 0] = sigmoid_scaled(qa.x - qa.y, 0.5f);
        fl[4 * j + 1] = sigmoid_scaled(qa.z - qa.w, 0.5f);
        fl[4 * j + 2] = sigmoid_scaled(qb.x - qb.y, 0.5f);
        fl[4 * j + 3] = sigmoid_scaled(qb.z - qb.w, 0.5f);

        // seg=2
        float t0 = qa.x + qa.y, t1 = qa.z + qa.w;
        float t2 = qb.x + qb.y, t3 = qb.z + qb.w;
        a2h[2 * j + 0] = sigmoid_scaled(t0 - t1, 0.25f);
        a2h[2 * j + 1] = sigmoid_scaled(t2 - t3, 0.25f);

        // seg=4
        float u0 = t0 + t1, u1 = t2 + t3;
        a4h[j] = sigmoid_scaled(u0 - u1, 0.125f);

        // seg=8..128 butterfly on the lane's 8-sum
        float Q = u0 + u1;
        float Bacc, o;
        o = __shfl_xor_sync(0xffffffffu, Q, 1);
        Bacc = sigmoid_scaled(Q - o, 1.0f / 16.0f);    Q += o;
        o = __shfl_xor_sync(0xffffffffu, Q, 2);
        Bacc *= sigmoid_scaled(Q - o, 1.0f / 32.0f);   Q += o;
        o = __shfl_xor_sync(0xffffffffu, Q, 4);
        Bacc *= sigmoid_scaled(Q - o, 1.0f / 64.0f);   Q += o;
        o = __shfl_xor_sync(0xffffffffu, Q, 8);
        Bacc *= sigmoid_scaled(Q - o, 1.0f / 128.0f);  Q += o;
        o = __shfl_xor_sync(0xffffffffu, Q, 16);
        Bacc *= sigmoid_scaled(Q - o, 1.0f / 256.0f);  Q += o;
        Bf[j] = Bacc;
        Rs[j] = Q;   // full 256-span sum, uniform across lanes
    }

    // ---- top levels (lane-uniform): seg=256 and seg=512 ----
    float c0 = sigmoid_scaled(Rs[0] - Rs[1], 1.0f / 512.0f);
    float c1 = sigmoid_scaled(Rs[2] - Rs[3], 1.0f / 512.0f);
    float W0 = Rs[0] + Rs[1], W1 = Rs[2] + Rs[3];
    float d  = sigmoid_scaled(W0 - W1, 1.0f / 1024.0f);

    float T[4];
    T[0] = d * c0;
    T[1] = d - T[0];
    float e = 1.0f - d;
    T[2] = e * c1;
    T[3] = e - T[2];

    // ---- downsweep + store (same addressing as loads: fully streamed) ----
#pragma unroll
    for (int j = 0; j < 4; j++) {
        float base = T[j] * Bf[j];
        float P0 = base * a4h[j];
        float P1 = base - P0;
        float q0 = P0 * a2h[2 * j];     float q1 = P0 - q0;
        float q2 = P1 * a2h[2 * j + 1]; float q3 = P1 - q2;

        float4 w0, w1;
        w0.x = q0 * fl[4 * j + 0]; w0.y = q0 - w0.x;
        w0.z = q1 * fl[4 * j + 1]; w0.w = q1 - w0.z;
        w1.x = q2 * fl[4 * j + 2]; w1.y = q2 - w1.x;
        w1.z = q3 * fl[4 * j + 3]; w1.w = q3 - w1.z;

        gout[j * 64 + 2 * lane]     = w0;
        gout[j * 64 + 2 * lane + 1] = w1;
    }
}

extern "C" void kernel_launch(void* const* d_in, const int* in_sizes, int n_in,
                              void* d_out, int out_size) {
    (void)in_sizes; (void)n_in; (void)out_size;
    const float* in = (const float*)d_in[0];
    float* out = (float*)d_out;
    // 32768 rows, 1 row per warp, 8 warps per block -> 4096 blocks
    soft_tree_kernel<<<BATCH_N / 8, 256>>>(in, out);
}

// round 12
// speedup vs baseline: 1.1059x; 1.1059x over previous
#include <cuda_runtime.h>
#include <cuda_bf16.h>

// SoftEmbeddedDecisionRules: balanced binary hierarchy over C=1024 classes.
// Fully-coalesced zero-smem design: one row per warp. Row = 8 half-spans of
// 128 classes; lane L owns chunk L (4 classes) of every half-span, so all
// 8 LDG.128 and 8 STG.128 are perfectly coalesced (4 lines/instr).
// seg 1/2: lane-local. seg 4..64: 5-step shfl butterfly per half-span
// (factor product accumulated immediately). seg 128/256/512: lane-uniform
// on the eight 128-sums. sigmoid(x/seg) = 0.5*tanh(x/(2seg)) + 0.5 —
// one MUFU per sigmoid. No shared memory, no barriers, no launch clamp.

#define BATCH_N 32768
#define NCLASS 1024

__device__ __forceinline__ float sigmoid_scaled(float d, float inv2seg) {
    float t;
    asm("tanh.approx.f32 %0, %1;" : "=f"(t) : "f"(d * inv2seg));
    return fmaf(0.5f, t, 0.5f);
}

__global__ void __launch_bounds__(256)
soft_tree_kernel(const float* __restrict__ in, float* __restrict__ out) {
    const int warp = (blockIdx.x * blockDim.x + threadIdx.x) >> 5;
    const int lane = threadIdx.x & 31;

    const float4* gin  = reinterpret_cast<const float4*>(in  + (size_t)warp * NCLASS);
    float4*       gout = reinterpret_cast<float4*>(out + (size_t)warp * NCLASS);

    float fl0[8], fl1[8];  // leaf factors (2 per owned chunk, per half-span)
    float a2[8];           // seg=2 factor (1 per chunk)
    float Bf[8];           // accumulated butterfly factors seg 4..64
    float H[8];            // 128-sums (lane-uniform after butterfly)

#pragma unroll
    for (int s = 0; s < 8; s++) {
        float4 q = gin[s * 32 + lane];          // coalesced

        // seg=1 leaves
        fl0[s] = sigmoid_scaled(q.x - q.y, 0.5f);
        fl1[s] = sigmoid_scaled(q.z - q.w, 0.5f);

        // seg=2
        float t0 = q.x + q.y, t1 = q.z + q.w;
        a2[s] = sigmoid_scaled(t0 - t1, 0.25f);

        // butterfly: seg = 4, 8, 16, 32, 64
        float u = t0 + t1;                       // lane's 4-sum
        float B, o;
        o = __shfl_xor_sync(0xffffffffu, u, 1);
        B  = sigmoid_scaled(u - o, 1.0f / 8.0f);    u += o;
        o = __shfl_xor_sync(0xffffffffu, u, 2);
        B *= sigmoid_scaled(u - o, 1.0f / 16.0f);   u += o;
        o = __shfl_xor_sync(0xffffffffu, u, 4);
        B *= sigmoid_scaled(u - o, 1.0f / 32.0f);   u += o;
        o = __shfl_xor_sync(0xffffffffu, u, 8);
        B *= sigmoid_scaled(u - o, 1.0f / 64.0f);   u += o;
        o = __shfl_xor_sync(0xffffffffu, u, 16);
        B *= sigmoid_scaled(u - o, 1.0f / 128.0f);  u += o;
        Bf[s] = B;
        H[s]  = u;                               // 128-sum, lane-uniform
    }

    // ---- top levels (lane-uniform): seg = 128, 256, 512 ----
    float f0 = sigmoid_scaled(H[0] - H[1], 1.0f / 256.0f);
    float f1 = sigmoid_scaled(H[2] - H[3], 1.0f / 256.0f);
    float f2 = sigmoid_scaled(H[4] - H[5], 1.0f / 256.0f);
    float f3 = sigmoid_scaled(H[6] - H[7], 1.0f / 256.0f);
    float Q0 = H[0] + H[1], Q1 = H[2] + H[3];
    float Q2 = H[4] + H[5], Q3 = H[6] + H[7];
    float g0 = sigmoid_scaled(Q0 - Q1, 1.0f / 512.0f);
    float g1 = sigmoid_scaled(Q2 - Q3, 1.0f / 512.0f);
    float d  = sigmoid_scaled((Q0 + Q1) - (Q2 + Q3), 1.0f / 1024.0f);

    // path products down to each half-span
    float e  = 1.0f - d;
    float i0 = d * g0, i1 = d - i0;      // 256-spans 0,1
    float i2 = e * g1, i3 = e - i2;      // 256-spans 2,3
    float T[8];
    T[0] = i0 * f0;  T[1] = i0 - T[0];
    T[2] = i1 * f1;  T[3] = i1 - T[2];
    T[4] = i2 * f2;  T[5] = i2 - T[4];
    T[6] = i3 * f3;  T[7] = i3 - T[6];

    // ---- downsweep + coalesced store ----
#pragma unroll
    for (int s = 0; s < 8; s++) {
        float P  = T[s] * Bf[s];        // prob of lane's 4-class block
        float p0 = P * a2[s];           // left 2-class pair
        float p1 = P - p0;              // right 2-class pair

        float4 w;
        w.x = p0 * fl0[s];  w.y = p0 - w.x;
        w.z = p1 * fl1[s];  w.w = p1 - w.z;
        gout[s * 32 + lane] = w;        // coalesced
    }
}

extern "C" void kernel_launch(void* const* d_in, const int* in_sizes, int n_in,
                              void* d_out, int out_size) {
    (void)in_sizes; (void)n_in; (void)out_size;
    const float* in = (const float*)d_in[0];
    float* out = (float*)d_out;
    // 32768 rows, 1 row per warp, 8 warps per block -> 4096 blocks
    soft_tree_kernel<<<BATCH_N / 8, 256>>>(in, out);
}